// round 14
// baseline (speedup 1.0000x reference)
#include <cuda_runtime.h>

#define BSZ 8
#define SEQ 4096
#define NH 32
#define HD 128
#define QLR 1536
#define NQ (NH*HD)      // 4096
#define KVROW (NH*256)  // floats per (b,s) row = 8192
#define NCHUNK 8
#define CHUNK (SEQ/NCHUNK)   // 512

#define RB 16            // r-split blocks for qproj
#define CB 32            // col blocks (128 cols each)
#define RPB (QLR/RB)     // 96 rows per block
#define RPW (RPB/8)      // 12 rows per warp

// Device-global scratch (no allocation allowed)
__device__ __align__(16) float g_qpart[RB * BSZ * NQ];        // 2 MB split-K partials
__device__ __align__(16) float g_po[BSZ * NH * NCHUNK * HD];  // unnormalized partial outputs
__device__ float g_pm[BSZ * NH * NCHUNK];                     // partial max
__device__ float g_ps[BSZ * NH * NCHUNK];                     // partial expsum

// ---------------------------------------------------------------------------
// qproj stage 1: split-K partial GEMM. grid = CB*RB = 512 CTAs x 256 thr.
// hs slice staged in smem (transposed); all 12 W float4 loads front-batched.
// launch_bounds(256,2) -> up to 128 regs so the load batch stays in flight.
// ---------------------------------------------------------------------------
__global__ __launch_bounds__(256, 2) void qproj1_kernel(const float* __restrict__ hs,
                                                        const float* __restrict__ W)
{
    __shared__ float4 part[8][32][BSZ];   // 32 KB
    __shared__ float  hs_s[RPB * BSZ];    // 3 KB, layout [r][b]

    const int cb   = blockIdx.x & (CB - 1);
    const int rb   = blockIdx.x >> 5;
    const int tid  = threadIdx.x;
    const int w    = tid >> 5;
    const int lane = tid & 31;

    const int n4 = cb * 128 + lane * 4;
    const int r0 = rb * RPB;

    // Stage hs[b][r0 .. r0+95] -> hs_s[r][b] (transposed). 192 float4 loads.
    if (tid < 192) {
        const int b = tid / 24;            // 0..7
        const int i = tid % 24;            // float4 index within 96 rows
        const float4 v = *(const float4*)(&hs[b * QLR + r0 + 4 * i]);
        hs_s[(4 * i + 0) * BSZ + b] = v.x;
        hs_s[(4 * i + 1) * BSZ + b] = v.y;
        hs_s[(4 * i + 2) * BSZ + b] = v.z;
        hs_s[(4 * i + 3) * BSZ + b] = v.w;
    }
    __syncthreads();

    // Front-batched W loads: 12 independent LDG.128 in the scoreboard.
    float4 wq[RPW];
#pragma unroll
    for (int rr = 0; rr < RPW; ++rr)
        wq[rr] = *(const float4*)(&W[(size_t)(r0 + w * RPW + rr) * NQ + n4]);

    float4 acc[BSZ];
#pragma unroll
    for (int b = 0; b < BSZ; ++b) acc[b] = make_float4(0.f, 0.f, 0.f, 0.f);

#pragma unroll
    for (int rr = 0; rr < RPW; ++rr) {
        const float4* hrow = (const float4*)(&hs_s[(w * RPW + rr) * BSZ]);
        const float4 h0 = hrow[0];         // b 0..3 (broadcast LDS.128)
        const float4 h1 = hrow[1];         // b 4..7
        const float4 w4 = wq[rr];
        acc[0].x += h0.x * w4.x; acc[0].y += h0.x * w4.y; acc[0].z += h0.x * w4.z; acc[0].w += h0.x * w4.w;
        acc[1].x += h0.y * w4.x; acc[1].y += h0.y * w4.y; acc[1].z += h0.y * w4.z; acc[1].w += h0.y * w4.w;
        acc[2].x += h0.z * w4.x; acc[2].y += h0.z * w4.y; acc[2].z += h0.z * w4.z; acc[2].w += h0.z * w4.w;
        acc[3].x += h0.w * w4.x; acc[3].y += h0.w * w4.y; acc[3].z += h0.w * w4.z; acc[3].w += h0.w * w4.w;
        acc[4].x += h1.x * w4.x; acc[4].y += h1.x * w4.y; acc[4].z += h1.x * w4.z; acc[4].w += h1.x * w4.w;
        acc[5].x += h1.y * w4.x; acc[5].y += h1.y * w4.y; acc[5].z += h1.y * w4.z; acc[5].w += h1.y * w4.w;
        acc[6].x += h1.z * w4.x; acc[6].y += h1.z * w4.y; acc[6].z += h1.z * w4.z; acc[6].w += h1.z * w4.w;
        acc[7].x += h1.w * w4.x; acc[7].y += h1.w * w4.y; acc[7].z += h1.w * w4.z; acc[7].w += h1.w * w4.w;
    }

#pragma unroll
    for (int b = 0; b < BSZ; ++b) part[w][lane][b] = acc[b];
    __syncthreads();

    {
        const int b2 = tid >> 5;
        const int l2 = tid & 31;
        float4 s = part[0][l2][b2];
#pragma unroll
        for (int ww = 1; ww < 8; ++ww) {
            const float4 t = part[ww][l2][b2];
            s.x += t.x; s.y += t.y; s.z += t.z; s.w += t.w;
        }
        const int n = cb * 128 + l2 * 4;
        *(float4*)(&g_qpart[((size_t)rb * BSZ + b2) * NQ + n]) = s;
    }
}

// ---------------------------------------------------------------------------
// attention: split-KV with fused q-reduce prologue. grid = BSZ*NH*NCHUNK
// = 2048 CTAs, 256 thr. Plain cached loads (no .cs — measured regression).
// ---------------------------------------------------------------------------
__global__ __launch_bounds__(256) void attn_kernel(const float* __restrict__ kv,
                                                   const float* __restrict__ bq)
{
    __shared__ float  sc[CHUNK];          // 2 KB
    __shared__ float4 part[8][32];        // 4 KB
    __shared__ float  red[8];
    __shared__ float  qsm[HD];

    const int id   = blockIdx.x;          // (b*NH + h)*NCHUNK + c
    const int c    = id & (NCHUNK - 1);
    const int bh   = id / NCHUNK;
    const int b    = bh >> 5;
    const int h    = bh & 31;
    const int tid  = threadIdx.x;
    const int w    = tid >> 5;
    const int lane = tid & 31;

    // ---------------- Prologue: reduce split-K q partials + bias ----------
    if (tid < 32) {
        const int n = h * HD + 4 * tid;
        float4 s = *(const float4*)(&bq[n]);
#pragma unroll
        for (int rb = 0; rb < RB; ++rb) {
            const float4 t = *(const float4*)(&g_qpart[((size_t)rb * BSZ + b) * NQ + n]);
            s.x += t.x; s.y += t.y; s.z += t.z; s.w += t.w;
        }
        *(float4*)(&qsm[4 * tid]) = s;
    }
    __syncthreads();

    const float4 qv = *(const float4*)(&qsm[4 * lane]);
    const float* kvb = kv + ((size_t)(b * SEQ + c * CHUNK) * NH + h) * 256;

    // ---------------- Pass 1: scores ----------------
#pragma unroll 2
    for (int i = 0; i < CHUNK / 32; ++i) {            // 16 iters, 4 s per warp
        float d0, d1, d2, d3;
        {
            const float4 k0 = *(const float4*)(kvb + (size_t)(w +  0 + 32*i) * KVROW + 4*lane);
            const float4 k1 = *(const float4*)(kvb + (size_t)(w +  8 + 32*i) * KVROW + 4*lane);
            const float4 k2 = *(const float4*)(kvb + (size_t)(w + 16 + 32*i) * KVROW + 4*lane);
            const float4 k3 = *(const float4*)(kvb + (size_t)(w + 24 + 32*i) * KVROW + 4*lane);
            d0 = k0.x*qv.x + k0.y*qv.y + k0.z*qv.z + k0.w*qv.w;
            d1 = k1.x*qv.x + k1.y*qv.y + k1.z*qv.z + k1.w*qv.w;
            d2 = k2.x*qv.x + k2.y*qv.y + k2.z*qv.z + k2.w*qv.w;
            d3 = k3.x*qv.x + k3.y*qv.y + k3.z*qv.z + k3.w*qv.w;
        }
        const float a0 = d0 + __shfl_xor_sync(0xffffffffu, d0, 16);
        const float a1 = d1 + __shfl_xor_sync(0xffffffffu, d1, 16);
        const float a2 = d2 + __shfl_xor_sync(0xffffffffu, d2, 16);
        const float a3 = d3 + __shfl_xor_sync(0xffffffffu, d3, 16);
        float m0 = (lane & 16) ? a1 : a0;
        float m1 = (lane & 16) ? a3 : a2;
        m0 += __shfl_xor_sync(0xffffffffu, m0, 8);
        m1 += __shfl_xor_sync(0xffffffffu, m1, 8);
        float n = (lane & 8) ? m1 : m0;
        n += __shfl_xor_sync(0xffffffffu, n, 4);
        n += __shfl_xor_sync(0xffffffffu, n, 2);
        n += __shfl_xor_sync(0xffffffffu, n, 1);
        if ((lane & 7) == 0) {
            const int j = ((lane >> 4) & 1) | (((lane >> 3) & 1) << 1);
            sc[w + 8 * j + 32 * i] = n;
        }
    }
    __syncthreads();

    // ---------------- Local softmax stats ----------------
    float m = -1e30f;
#pragma unroll
    for (int k = 0; k < CHUNK / 256; ++k)
        m = fmaxf(m, sc[tid + 256 * k]);
    m = fmaxf(m, __shfl_xor_sync(0xffffffffu, m, 16));
    m = fmaxf(m, __shfl_xor_sync(0xffffffffu, m, 8));
    m = fmaxf(m, __shfl_xor_sync(0xffffffffu, m, 4));
    m = fmaxf(m, __shfl_xor_sync(0xffffffffu, m, 2));
    m = fmaxf(m, __shfl_xor_sync(0xffffffffu, m, 1));
    if (lane == 0) red[w] = m;
    __syncthreads();

    float gmax = red[0];
#pragma unroll
    for (int ww = 1; ww < 8; ++ww) gmax = fmaxf(gmax, red[ww]);

    float lsum = 0.f;
#pragma unroll
    for (int k = 0; k < CHUNK / 256; ++k) {
        const float e = __expf(sc[tid + 256 * k] - gmax);
        sc[tid + 256 * k] = e;
        lsum += e;
    }
    lsum += __shfl_xor_sync(0xffffffffu, lsum, 16);
    lsum += __shfl_xor_sync(0xffffffffu, lsum, 8);
    lsum += __shfl_xor_sync(0xffffffffu, lsum, 4);
    lsum += __shfl_xor_sync(0xffffffffu, lsum, 2);
    lsum += __shfl_xor_sync(0xffffffffu, lsum, 1);
    __syncthreads();                  // done reading red (gmax)
    if (lane == 0) red[w] = lsum;
    __syncthreads();

    float total = red[0];
#pragma unroll
    for (int ww = 1; ww < 8; ++ww) total += red[ww];

    // ---------------- Pass 2: unnormalized output ----------------
    float4 acc0 = make_float4(0.f, 0.f, 0.f, 0.f);
    float4 acc1 = make_float4(0.f, 0.f, 0.f, 0.f);
    const float* vb = kvb + 128;
#pragma unroll 2
    for (int i = 0; i < CHUNK / 32; ++i) {
        {
            const int s = w + 32 * i;
            const float  p = sc[s];
            const float4 v = *(const float4*)(vb + (size_t)s * KVROW + 4 * lane);
            acc0.x += p * v.x; acc0.y += p * v.y; acc0.z += p * v.z; acc0.w += p * v.w;
        }
        {
            const int s = w + 8 + 32 * i;
            const float  p = sc[s];
            const float4 v = *(const float4*)(vb + (size_t)s * KVROW + 4 * lane);
            acc1.x += p * v.x; acc1.y += p * v.y; acc1.z += p * v.z; acc1.w += p * v.w;
        }
        {
            const int s = w + 16 + 32 * i;
            const float  p = sc[s];
            const float4 v = *(const float4*)(vb + (size_t)s * KVROW + 4 * lane);
            acc0.x += p * v.x; acc0.y += p * v.y; acc0.z += p * v.z; acc0.w += p * v.w;
        }
        {
            const int s = w + 24 + 32 * i;
            const float  p = sc[s];
            const float4 v = *(const float4*)(vb + (size_t)s * KVROW + 4 * lane);
            acc1.x += p * v.x; acc1.y += p * v.y; acc1.z += p * v.z; acc1.w += p * v.w;
        }
    }
    acc0.x += acc1.x; acc0.y += acc1.y; acc0.z += acc1.z; acc0.w += acc1.w;
    part[w][lane] = acc0;
    __syncthreads();

    if (tid < 32) {
        float4 r = part[0][tid];
#pragma unroll
        for (int ww = 1; ww < 8; ++ww) {
            const float4 t = part[ww][tid];
            r.x += t.x; r.y += t.y; r.z += t.z; r.w += t.w;
        }
        *(float4*)(&g_po[(size_t)id * HD + 4 * tid]) = r;   // unnormalized
        if (tid == 0) { g_pm[id] = gmax; g_ps[id] = total; }
    }
}

// ---------------------------------------------------------------------------
// combine: 64 blocks x 128 threads, one float4 of output per thread.
// ---------------------------------------------------------------------------
__global__ __launch_bounds__(128) void combine_kernel(float* __restrict__ out)
{
    const int idx = blockIdx.x * 128 + threadIdx.x;   // 0 .. 8191
    const int bh  = idx >> 5;                         // b*NH + h
    const int d4  = (idx & 31) * 4;
    const int i0  = bh * NCHUNK;

    float gm = g_pm[i0];
#pragma unroll
    for (int c = 1; c < NCHUNK; ++c) gm = fmaxf(gm, g_pm[i0 + c]);

    float den = 0.f;
    float4 num = make_float4(0.f, 0.f, 0.f, 0.f);
#pragma unroll
    for (int c = 0; c < NCHUNK; ++c) {
        const float e = __expf(g_pm[i0 + c] - gm);
        den += e * g_ps[i0 + c];
        const float4 t = *(const float4*)(&g_po[(size_t)(i0 + c) * HD + d4]);
        num.x += e * t.x; num.y += e * t.y; num.z += e * t.z; num.w += e * t.w;
    }
    const float inv = 1.f / den;
    num.x *= inv; num.y *= inv; num.z *= inv; num.w *= inv;
    *(float4*)(&out[(size_t)bh * HD + d4]) = num;
}

// ---------------------------------------------------------------------------
extern "C" void kernel_launch(void* const* d_in, const int* in_sizes, int n_in,
                              void* d_out, int out_size)
{
    const float* hs = (const float*)d_in[0];  // (8, 1536)
    const float* kv = (const float*)d_in[1];  // (8, 4096, 32, 256)
    const float* W  = (const float*)d_in[2];  // (1536, 4096)
    const float* bq = (const float*)d_in[3];  // (4096,)
    float* out = (float*)d_out;               // (8, 4096)

    qproj1_kernel<<<CB * RB, 256>>>(hs, W);
    attn_kernel<<<BSZ * NH * NCHUNK, 256>>>(kv, bq);
    combine_kernel<<<64, 128>>>(out);
}

// round 16
// speedup vs baseline: 1.0539x; 1.0539x over previous
#include <cuda_runtime.h>

#define BSZ 8
#define SEQ 4096
#define NH 32
#define HD 128
#define QLR 1536
#define NQ (NH*HD)      // 4096
#define KVROW (NH*256)  // floats per (b,s) row = 8192
#define NCHUNK 8
#define CHUNK (SEQ/NCHUNK)   // 512

#define RB 8             // r-split blocks for qproj
#define CB 32            // col blocks (128 cols each)
#define RPB (QLR/RB)     // 192 rows per block
#define RPW (RPB/8)      // 24 rows per warp
#define BT 8             // rows per load batch
// 3 batches per warp, double-buffered

// Device-global scratch (no allocation allowed)
__device__ __align__(16) float g_qpart[RB * BSZ * NQ];        // 1 MB split-K partials
__device__ __align__(16) float g_po[BSZ * NH * NCHUNK * HD];  // unnormalized partial outputs
__device__ float g_pm[BSZ * NH * NCHUNK];                     // partial max
__device__ float g_ps[BSZ * NH * NCHUNK];                     // partial expsum

// ---------------------------------------------------------------------------
// FMA block for one 8-row batch: buf[j] holds W row (rbase+j), cols n4..n4+3.
// ---------------------------------------------------------------------------
__device__ __forceinline__ void fma_batch(const float4* __restrict__ buf,
                                          const float (*hs_s)[BSZ],
                                          int rbase, float4* acc)
{
#pragma unroll
    for (int j = 0; j < BT; ++j) {
        const float4 h0 = *(const float4*)(&hs_s[rbase + j][0]);  // b 0..3
        const float4 h1 = *(const float4*)(&hs_s[rbase + j][4]);  // b 4..7
        const float4 w4 = buf[j];
        acc[0].x += h0.x * w4.x; acc[0].y += h0.x * w4.y; acc[0].z += h0.x * w4.z; acc[0].w += h0.x * w4.w;
        acc[1].x += h0.y * w4.x; acc[1].y += h0.y * w4.y; acc[1].z += h0.y * w4.z; acc[1].w += h0.y * w4.w;
        acc[2].x += h0.z * w4.x; acc[2].y += h0.z * w4.y; acc[2].z += h0.z * w4.z; acc[2].w += h0.z * w4.w;
        acc[3].x += h0.w * w4.x; acc[3].y += h0.w * w4.y; acc[3].z += h0.w * w4.z; acc[3].w += h0.w * w4.w;
        acc[4].x += h1.x * w4.x; acc[4].y += h1.x * w4.y; acc[4].z += h1.x * w4.z; acc[4].w += h1.x * w4.w;
        acc[5].x += h1.y * w4.x; acc[5].y += h1.y * w4.y; acc[5].z += h1.y * w4.z; acc[5].w += h1.y * w4.w;
        acc[6].x += h1.z * w4.x; acc[6].y += h1.z * w4.y; acc[6].z += h1.z * w4.z; acc[6].w += h1.z * w4.w;
        acc[7].x += h1.w * w4.x; acc[7].y += h1.w * w4.y; acc[7].z += h1.w * w4.z; acc[7].w += h1.w * w4.w;
    }
}

// ---------------------------------------------------------------------------
// qproj stage 1: split-K streaming GEMM. grid = CB*RB = 256 CTAs x 256 thr,
// all resident in one wave (occ 2). Warp owns 24 rows; 3 batches of 8
// register-double-buffered W loads keep DRAM traffic in flight continuously.
// Bank-conflict-free smem reduction layout [warp][b][col4].
// ---------------------------------------------------------------------------
__global__ __launch_bounds__(256, 2) void qproj1_kernel(const float* __restrict__ hs,
                                                        const float* __restrict__ W)
{
    __shared__ float4 part[8][BSZ][32];   // [warp][b][col4] = 32 KB
    __shared__ float  hs_s[RPB][BSZ];     // 6 KB, [r][b]

    const int cb   = blockIdx.x & (CB - 1);
    const int rb   = blockIdx.x >> 5;
    const int tid  = threadIdx.x;
    const int w    = tid >> 5;
    const int lane = tid & 31;

    const int n4 = cb * 128 + lane * 4;
    const int r0 = rb * RPB;

    // Stage hs[b][r0 .. r0+191] -> hs_s[r][b] (transposed). 384 float4 loads.
    for (int idx = tid; idx < (RPB / 4) * BSZ; idx += 256) {
        const int b = idx / (RPB / 4);
        const int i = idx % (RPB / 4);
        const float4 v = *(const float4*)(&hs[b * QLR + r0 + 4 * i]);
        hs_s[4 * i + 0][b] = v.x;
        hs_s[4 * i + 1][b] = v.y;
        hs_s[4 * i + 2][b] = v.z;
        hs_s[4 * i + 3][b] = v.w;
    }
    __syncthreads();

    const int rw = w * RPW;                               // warp's row base (local)
    const float* Wb = &W[(size_t)(r0 + rw) * NQ + n4];

    float4 bufA[BT], bufB[BT];
    // issue batches 0 and 1 up front (16 independent LDG.128)
#pragma unroll
    for (int j = 0; j < BT; ++j) bufA[j] = *(const float4*)(Wb + (size_t)j * NQ);
#pragma unroll
    for (int j = 0; j < BT; ++j) bufB[j] = *(const float4*)(Wb + (size_t)(BT + j) * NQ);

    float4 acc[BSZ];
#pragma unroll
    for (int b = 0; b < BSZ; ++b) acc[b] = make_float4(0.f, 0.f, 0.f, 0.f);

    // compute batch 0 while batch 1 is in flight; prefetch batch 2 behind it
    fma_batch(bufA, hs_s, rw, acc);
#pragma unroll
    for (int j = 0; j < BT; ++j) bufA[j] = *(const float4*)(Wb + (size_t)(2 * BT + j) * NQ);
    fma_batch(bufB, hs_s, rw + BT, acc);
    fma_batch(bufA, hs_s, rw + 2 * BT, acc);

    // conflict-free partials: store [warp][b][lane] (contiguous per lane)
#pragma unroll
    for (int b = 0; b < BSZ; ++b) part[w][b][lane] = acc[b];
    __syncthreads();

    // reduce: warp b2 handles batch b2; lane l2 handles col quad l2
    {
        const int b2 = tid >> 5;
        const int l2 = tid & 31;
        float4 s = part[0][b2][l2];
#pragma unroll
        for (int ww = 1; ww < 8; ++ww) {
            const float4 t = part[ww][b2][l2];
            s.x += t.x; s.y += t.y; s.z += t.z; s.w += t.w;
        }
        *(float4*)(&g_qpart[((size_t)rb * BSZ + b2) * NQ + cb * 128 + l2 * 4]) = s;
    }
}

// ---------------------------------------------------------------------------
// attention: split-KV with fused q-reduce prologue. grid = BSZ*NH*NCHUNK
// = 2048 CTAs, 256 thr. Plain cached loads (no .cs — measured regression).
// ---------------------------------------------------------------------------
__global__ __launch_bounds__(256) void attn_kernel(const float* __restrict__ kv,
                                                   const float* __restrict__ bq)
{
    __shared__ float  sc[CHUNK];          // 2 KB
    __shared__ float4 part[8][32];        // 4 KB
    __shared__ float  red[8];
    __shared__ float  qsm[HD];

    const int id   = blockIdx.x;          // (b*NH + h)*NCHUNK + c
    const int c    = id & (NCHUNK - 1);
    const int bh   = id / NCHUNK;
    const int b    = bh >> 5;
    const int h    = bh & 31;
    const int tid  = threadIdx.x;
    const int w    = tid >> 5;
    const int lane = tid & 31;

    // ---------------- Prologue: reduce split-K q partials + bias ----------
    if (tid < 32) {
        const int n = h * HD + 4 * tid;
        float4 s = *(const float4*)(&bq[n]);
#pragma unroll
        for (int rb = 0; rb < RB; ++rb) {
            const float4 t = *(const float4*)(&g_qpart[((size_t)rb * BSZ + b) * NQ + n]);
            s.x += t.x; s.y += t.y; s.z += t.z; s.w += t.w;
        }
        *(float4*)(&qsm[4 * tid]) = s;
    }
    __syncthreads();

    const float4 qv = *(const float4*)(&qsm[4 * lane]);
    const float* kvb = kv + ((size_t)(b * SEQ + c * CHUNK) * NH + h) * 256;

    // ---------------- Pass 1: scores ----------------
#pragma unroll 2
    for (int i = 0; i < CHUNK / 32; ++i) {            // 16 iters, 4 s per warp
        float d0, d1, d2, d3;
        {
            const float4 k0 = *(const float4*)(kvb + (size_t)(w +  0 + 32*i) * KVROW + 4*lane);
            const float4 k1 = *(const float4*)(kvb + (size_t)(w +  8 + 32*i) * KVROW + 4*lane);
            const float4 k2 = *(const float4*)(kvb + (size_t)(w + 16 + 32*i) * KVROW + 4*lane);
            const float4 k3 = *(const float4*)(kvb + (size_t)(w + 24 + 32*i) * KVROW + 4*lane);
            d0 = k0.x*qv.x + k0.y*qv.y + k0.z*qv.z + k0.w*qv.w;
            d1 = k1.x*qv.x + k1.y*qv.y + k1.z*qv.z + k1.w*qv.w;
            d2 = k2.x*qv.x + k2.y*qv.y + k2.z*qv.z + k2.w*qv.w;
            d3 = k3.x*qv.x + k3.y*qv.y + k3.z*qv.z + k3.w*qv.w;
        }
        const float a0 = d0 + __shfl_xor_sync(0xffffffffu, d0, 16);
        const float a1 = d1 + __shfl_xor_sync(0xffffffffu, d1, 16);
        const float a2 = d2 + __shfl_xor_sync(0xffffffffu, d2, 16);
        const float a3 = d3 + __shfl_xor_sync(0xffffffffu, d3, 16);
        float m0 = (lane & 16) ? a1 : a0;
        float m1 = (lane & 16) ? a3 : a2;
        m0 += __shfl_xor_sync(0xffffffffu, m0, 8);
        m1 += __shfl_xor_sync(0xffffffffu, m1, 8);
        float n = (lane & 8) ? m1 : m0;
        n += __shfl_xor_sync(0xffffffffu, n, 4);
        n += __shfl_xor_sync(0xffffffffu, n, 2);
        n += __shfl_xor_sync(0xffffffffu, n, 1);
        if ((lane & 7) == 0) {
            const int j = ((lane >> 4) & 1) | (((lane >> 3) & 1) << 1);
            sc[w + 8 * j + 32 * i] = n;
        }
    }
    __syncthreads();

    // ---------------- Local softmax stats ----------------
    float m = -1e30f;
#pragma unroll
    for (int k = 0; k < CHUNK / 256; ++k)
        m = fmaxf(m, sc[tid + 256 * k]);
    m = fmaxf(m, __shfl_xor_sync(0xffffffffu, m, 16));
    m = fmaxf(m, __shfl_xor_sync(0xffffffffu, m, 8));
    m = fmaxf(m, __shfl_xor_sync(0xffffffffu, m, 4));
    m = fmaxf(m, __shfl_xor_sync(0xffffffffu, m, 2));
    m = fmaxf(m, __shfl_xor_sync(0xffffffffu, m, 1));
    if (lane == 0) red[w] = m;
    __syncthreads();

    float gmax = red[0];
#pragma unroll
    for (int ww = 1; ww < 8; ++ww) gmax = fmaxf(gmax, red[ww]);

    float lsum = 0.f;
#pragma unroll
    for (int k = 0; k < CHUNK / 256; ++k) {
        const float e = __expf(sc[tid + 256 * k] - gmax);
        sc[tid + 256 * k] = e;
        lsum += e;
    }
    lsum += __shfl_xor_sync(0xffffffffu, lsum, 16);
    lsum += __shfl_xor_sync(0xffffffffu, lsum, 8);
    lsum += __shfl_xor_sync(0xffffffffu, lsum, 4);
    lsum += __shfl_xor_sync(0xffffffffu, lsum, 2);
    lsum += __shfl_xor_sync(0xffffffffu, lsum, 1);
    __syncthreads();                  // done reading red (gmax)
    if (lane == 0) red[w] = lsum;
    __syncthreads();

    float total = red[0];
#pragma unroll
    for (int ww = 1; ww < 8; ++ww) total += red[ww];

    // ---------------- Pass 2: unnormalized output ----------------
    float4 acc0 = make_float4(0.f, 0.f, 0.f, 0.f);
    float4 acc1 = make_float4(0.f, 0.f, 0.f, 0.f);
    const float* vb = kvb + 128;
#pragma unroll 2
    for (int i = 0; i < CHUNK / 32; ++i) {
        {
            const int s = w + 32 * i;
            const float  p = sc[s];
            const float4 v = *(const float4*)(vb + (size_t)s * KVROW + 4 * lane);
            acc0.x += p * v.x; acc0.y += p * v.y; acc0.z += p * v.z; acc0.w += p * v.w;
        }
        {
            const int s = w + 8 + 32 * i;
            const float  p = sc[s];
            const float4 v = *(const float4*)(vb + (size_t)s * KVROW + 4 * lane);
            acc1.x += p * v.x; acc1.y += p * v.y; acc1.z += p * v.z; acc1.w += p * v.w;
        }
        {
            const int s = w + 16 + 32 * i;
            const float  p = sc[s];
            const float4 v = *(const float4*)(vb + (size_t)s * KVROW + 4 * lane);
            acc0.x += p * v.x; acc0.y += p * v.y; acc0.z += p * v.z; acc0.w += p * v.w;
        }
        {
            const int s = w + 24 + 32 * i;
            const float  p = sc[s];
            const float4 v = *(const float4*)(vb + (size_t)s * KVROW + 4 * lane);
            acc1.x += p * v.x; acc1.y += p * v.y; acc1.z += p * v.z; acc1.w += p * v.w;
        }
    }
    acc0.x += acc1.x; acc0.y += acc1.y; acc0.z += acc1.z; acc0.w += acc1.w;
    part[w][lane] = acc0;
    __syncthreads();

    if (tid < 32) {
        float4 r = part[0][tid];
#pragma unroll
        for (int ww = 1; ww < 8; ++ww) {
            const float4 t = part[ww][tid];
            r.x += t.x; r.y += t.y; r.z += t.z; r.w += t.w;
        }
        *(float4*)(&g_po[(size_t)id * HD + 4 * tid]) = r;   // unnormalized
        if (tid == 0) { g_pm[id] = gmax; g_ps[id] = total; }
    }
}

// ---------------------------------------------------------------------------
// combine: 64 blocks x 128 threads, one float4 of output per thread.
// ---------------------------------------------------------------------------
__global__ __launch_bounds__(128) void combine_kernel(float* __restrict__ out)
{
    const int idx = blockIdx.x * 128 + threadIdx.x;   // 0 .. 8191
    const int bh  = idx >> 5;                         // b*NH + h
    const int d4  = (idx & 31) * 4;
    const int i0  = bh * NCHUNK;

    float gm = g_pm[i0];
#pragma unroll
    for (int c = 1; c < NCHUNK; ++c) gm = fmaxf(gm, g_pm[i0 + c]);

    float den = 0.f;
    float4 num = make_float4(0.f, 0.f, 0.f, 0.f);
#pragma unroll
    for (int c = 0; c < NCHUNK; ++c) {
        const float e = __expf(g_pm[i0 + c] - gm);
        den += e * g_ps[i0 + c];
        const float4 t = *(const float4*)(&g_po[(size_t)(i0 + c) * HD + d4]);
        num.x += e * t.x; num.y += e * t.y; num.z += e * t.z; num.w += e * t.w;
    }
    const float inv = 1.f / den;
    num.x *= inv; num.y *= inv; num.z *= inv; num.w *= inv;
    *(float4*)(&out[(size_t)bh * HD + d4]) = num;
}

// ---------------------------------------------------------------------------
extern "C" void kernel_launch(void* const* d_in, const int* in_sizes, int n_in,
                              void* d_out, int out_size)
{
    const float* hs = (const float*)d_in[0];  // (8, 1536)
    const float* kv = (const float*)d_in[1];  // (8, 4096, 32, 256)
    const float* W  = (const float*)d_in[2];  // (1536, 4096)
    const float* bq = (const float*)d_in[3];  // (4096,)
    float* out = (float*)d_out;               // (8, 4096)

    qproj1_kernel<<<CB * RB, 256>>>(hs, W);
    attn_kernel<<<BSZ * NH * NCHUNK, 256>>>(kv, bq);
    combine_kernel<<<64, 128>>>(out);
}